// round 11
// baseline (speedup 1.0000x reference)
#include <cuda_runtime.h>

// out[r] = (sum over 1024 elems of row r of x) * (sum of coeffs)
// x: (16, 4096, 1024) fp32 -> 65536 rows of 1024
// coeffs: (10, 1) fp32
//
// One warp per TWO adjacent rows (8KB). All EIGHT 256-bit evict_first
// loads are emitted in one asm block with 64 distinct output registers,
// forcing ptxas to keep every load in flight (per-lane MLP = 8 x 32B)
// before any arithmetic. Packed-double butterfly reduces both rows in
// 5 shuffles.

__global__ __launch_bounds__(256) void spline_rowsum2_v8mlp_kernel(
    const float* __restrict__ x,
    const float* __restrict__ coeffs,
    int n_coeffs,
    float* __restrict__ out,
    int npairs)
{
    int gwarp = (blockIdx.x * blockDim.x + threadIdx.x) >> 5;
    int lane  = threadIdx.x & 31;
    if (gwarp >= npairs) return;

    const float* base = x + (size_t)gwarp * 2048 + lane * 8;

    float a0, a1, a2, a3, a4, a5, a6, a7,
          a8, a9, a10, a11, a12, a13, a14, a15,
          a16, a17, a18, a19, a20, a21, a22, a23,
          a24, a25, a26, a27, a28, a29, a30, a31;
    float b0, b1, b2, b3, b4, b5, b6, b7,
          b8, b9, b10, b11, b12, b13, b14, b15,
          b16, b17, b18, b19, b20, b21, b22, b23,
          b24, b25, b26, b27, b28, b29, b30, b31;

    // 8 x 256-bit loads, one asm block -> 64 live dest regs.
    // Row A at +0..+3072 bytes, row B at +4096..+7168 bytes.
    asm volatile(
        "ld.global.nc.L2::evict_first.v8.b32 {%0,%1,%2,%3,%4,%5,%6,%7}, [%64];\n\t"
        "ld.global.nc.L2::evict_first.v8.b32 {%8,%9,%10,%11,%12,%13,%14,%15}, [%64+1024];\n\t"
        "ld.global.nc.L2::evict_first.v8.b32 {%16,%17,%18,%19,%20,%21,%22,%23}, [%64+2048];\n\t"
        "ld.global.nc.L2::evict_first.v8.b32 {%24,%25,%26,%27,%28,%29,%30,%31}, [%64+3072];\n\t"
        "ld.global.nc.L2::evict_first.v8.b32 {%32,%33,%34,%35,%36,%37,%38,%39}, [%64+4096];\n\t"
        "ld.global.nc.L2::evict_first.v8.b32 {%40,%41,%42,%43,%44,%45,%46,%47}, [%64+5120];\n\t"
        "ld.global.nc.L2::evict_first.v8.b32 {%48,%49,%50,%51,%52,%53,%54,%55}, [%64+6144];\n\t"
        "ld.global.nc.L2::evict_first.v8.b32 {%56,%57,%58,%59,%60,%61,%62,%63}, [%64+7168];"
        : "=f"(a0),  "=f"(a1),  "=f"(a2),  "=f"(a3),
          "=f"(a4),  "=f"(a5),  "=f"(a6),  "=f"(a7),
          "=f"(a8),  "=f"(a9),  "=f"(a10), "=f"(a11),
          "=f"(a12), "=f"(a13), "=f"(a14), "=f"(a15),
          "=f"(a16), "=f"(a17), "=f"(a18), "=f"(a19),
          "=f"(a20), "=f"(a21), "=f"(a22), "=f"(a23),
          "=f"(a24), "=f"(a25), "=f"(a26), "=f"(a27),
          "=f"(a28), "=f"(a29), "=f"(a30), "=f"(a31),
          "=f"(b0),  "=f"(b1),  "=f"(b2),  "=f"(b3),
          "=f"(b4),  "=f"(b5),  "=f"(b6),  "=f"(b7),
          "=f"(b8),  "=f"(b9),  "=f"(b10), "=f"(b11),
          "=f"(b12), "=f"(b13), "=f"(b14), "=f"(b15),
          "=f"(b16), "=f"(b17), "=f"(b18), "=f"(b19),
          "=f"(b20), "=f"(b21), "=f"(b22), "=f"(b23),
          "=f"(b24), "=f"(b25), "=f"(b26), "=f"(b27),
          "=f"(b28), "=f"(b29), "=f"(b30), "=f"(b31)
        : "l"(base));

    float sa = ((((a0  + a1)  + (a2  + a3))  + ((a4  + a5)  + (a6  + a7)))
             +  (((a8  + a9)  + (a10 + a11)) + ((a12 + a13) + (a14 + a15))))
             + ((((a16 + a17) + (a18 + a19)) + ((a20 + a21) + (a22 + a23)))
             +  (((a24 + a25) + (a26 + a27)) + ((a28 + a29) + (a30 + a31))));
    float sb = ((((b0  + b1)  + (b2  + b3))  + ((b4  + b5)  + (b6  + b7)))
             +  (((b8  + b9)  + (b10 + b11)) + ((b12 + b13) + (b14 + b15))))
             + ((((b16 + b17) + (b18 + b19)) + ((b20 + b21) + (b22 + b23)))
             +  (((b24 + b25) + (b26 + b27)) + ((b28 + b29) + (b30 + b31))));

    // Packed butterfly: both rows in 5 shuffles (8B each)
    float2 sv = make_float2(sa, sb);
    unsigned long long pk = *reinterpret_cast<unsigned long long*>(&sv);
#pragma unroll
    for (int off = 16; off; off >>= 1) {
        unsigned long long other = __shfl_xor_sync(0xFFFFFFFFu, pk, off);
        float2 o = *reinterpret_cast<float2*>(&other);
        float2 s = *reinterpret_cast<float2*>(&pk);
        s.x += o.x; s.y += o.y;
        pk = *reinterpret_cast<unsigned long long*>(&s);
    }
    float2 tot = *reinterpret_cast<float2*>(&pk);

    if (lane == 0) {
        float c = 0.0f;
        for (int i = 0; i < n_coeffs; i++) c += coeffs[i];
        out[2 * gwarp]     = tot.x * c;
        out[2 * gwarp + 1] = tot.y * c;
    }
}

extern "C" void kernel_launch(void* const* d_in, const int* in_sizes, int n_in,
                              void* d_out, int out_size)
{
    const float* x      = (const float*)d_in[0];
    const float* coeffs = (const float*)d_in[1];
    float* out          = (float*)d_out;

    int nrows    = in_sizes[0] / 1024;   // 65536
    int n_coeffs = in_sizes[1];          // 10
    int npairs   = nrows / 2;            // 32768

    // 8 warps (16 rows) per 256-thread block
    int blocks = (npairs + 7) / 8;       // 4096
    spline_rowsum2_v8mlp_kernel<<<blocks, 256>>>(x, coeffs, n_coeffs, out, npairs);
}

// round 12
// speedup vs baseline: 1.0098x; 1.0098x over previous
#include <cuda_runtime.h>

// out[r] = (sum over 1024 elems of row r of x) * (sum of coeffs)
// x: (16, 4096, 1024) fp32 -> 65536 rows of 1024
// coeffs: (10, 1) fp32
//
// FINAL (R9 config, best measured): one warp per row, fire-and-exit.
// All four 256-bit evict_first loads in a single asm block with 32
// distinct output registers -> guaranteed per-lane MLP of 4 x 32B before
// any arithmetic. Measured 6.75 TB/s = ~97% of the sm_103a LTS
// chip-throughput cap (~6300 B/cyc, path-independent), which is the
// true roofline for this zero-reuse stream — not the 8 TB/s HBM spec.

__global__ __launch_bounds__(256) void spline_rowsum_v8mlp_kernel(
    const float* __restrict__ x,
    const float* __restrict__ coeffs,
    int n_coeffs,
    float* __restrict__ out,
    int nrows)
{
    int gwarp = (blockIdx.x * blockDim.x + threadIdx.x) >> 5;
    int lane  = threadIdx.x & 31;
    if (gwarp >= nrows) return;

    const float* row = x + (size_t)gwarp * 1024 + lane * 8;

    float f0, f1, f2, f3, f4, f5, f6, f7,
          f8, f9, f10, f11, f12, f13, f14, f15,
          f16, f17, f18, f19, f20, f21, f22, f23,
          f24, f25, f26, f27, f28, f29, f30, f31;

    // 4 x 256-bit loads, one asm block -> 32 live dest regs, issued
    // back-to-back. Offsets in bytes: 256 floats = 1024B apart.
    asm volatile(
        "ld.global.nc.L2::evict_first.v8.b32 {%0,%1,%2,%3,%4,%5,%6,%7}, [%32];\n\t"
        "ld.global.nc.L2::evict_first.v8.b32 {%8,%9,%10,%11,%12,%13,%14,%15}, [%32+1024];\n\t"
        "ld.global.nc.L2::evict_first.v8.b32 {%16,%17,%18,%19,%20,%21,%22,%23}, [%32+2048];\n\t"
        "ld.global.nc.L2::evict_first.v8.b32 {%24,%25,%26,%27,%28,%29,%30,%31}, [%32+3072];"
        : "=f"(f0),  "=f"(f1),  "=f"(f2),  "=f"(f3),
          "=f"(f4),  "=f"(f5),  "=f"(f6),  "=f"(f7),
          "=f"(f8),  "=f"(f9),  "=f"(f10), "=f"(f11),
          "=f"(f12), "=f"(f13), "=f"(f14), "=f"(f15),
          "=f"(f16), "=f"(f17), "=f"(f18), "=f"(f19),
          "=f"(f20), "=f"(f21), "=f"(f22), "=f"(f23),
          "=f"(f24), "=f"(f25), "=f"(f26), "=f"(f27),
          "=f"(f28), "=f"(f29), "=f"(f30), "=f"(f31)
        : "l"(row));

    float s0 = ((f0  + f1)  + (f2  + f3))  + ((f4  + f5)  + (f6  + f7));
    float s1 = ((f8  + f9)  + (f10 + f11)) + ((f12 + f13) + (f14 + f15));
    float s2 = ((f16 + f17) + (f18 + f19)) + ((f20 + f21) + (f22 + f23));
    float s3 = ((f24 + f25) + (f26 + f27)) + ((f28 + f29) + (f30 + f31));
    float s = (s0 + s1) + (s2 + s3);

    // butterfly warp reduction
#pragma unroll
    for (int off = 16; off; off >>= 1)
        s += __shfl_xor_sync(0xFFFFFFFFu, s, off);

    if (lane == 0) {
        float c = 0.0f;
        for (int i = 0; i < n_coeffs; i++) c += coeffs[i];
        out[gwarp] = s * c;
    }
}

extern "C" void kernel_launch(void* const* d_in, const int* in_sizes, int n_in,
                              void* d_out, int out_size)
{
    const float* x      = (const float*)d_in[0];
    const float* coeffs = (const float*)d_in[1];
    float* out          = (float*)d_out;

    int nrows    = in_sizes[0] / 1024;   // 65536
    int n_coeffs = in_sizes[1];          // 10

    // 8 warps (rows) per 256-thread block
    int blocks = (nrows + 7) / 8;        // 8192
    spline_rowsum_v8mlp_kernel<<<blocks, 256>>>(x, coeffs, n_coeffs, out, nrows);
}

// round 13
// speedup vs baseline: 1.0307x; 1.0207x over previous
#include <cuda_runtime.h>

// out[r] = (sum over 1024 elems of row r of x) * (sum of coeffs)
// x: (16, 4096, 1024) fp32 -> 65536 rows of 1024
// coeffs: (10, 1) fp32
//
// R9 load schedule (best measured, LTS-cap-bound): one warp per row,
// four 256-bit evict_first loads in a single asm block with 32 distinct
// output registers (guaranteed per-lane MLP = 4 x 32B). This round:
// 512-thread blocks (16 warps/rows per block) to halve block count and
// trim launch/tail overhead; load path untouched.

__global__ __launch_bounds__(512) void spline_rowsum_v8mlp_kernel(
    const float* __restrict__ x,
    const float* __restrict__ coeffs,
    int n_coeffs,
    float* __restrict__ out,
    int nrows)
{
    int gwarp = (blockIdx.x * blockDim.x + threadIdx.x) >> 5;
    int lane  = threadIdx.x & 31;
    if (gwarp >= nrows) return;

    const float* row = x + (size_t)gwarp * 1024 + lane * 8;

    float f0, f1, f2, f3, f4, f5, f6, f7,
          f8, f9, f10, f11, f12, f13, f14, f15,
          f16, f17, f18, f19, f20, f21, f22, f23,
          f24, f25, f26, f27, f28, f29, f30, f31;

    // 4 x 256-bit loads, one asm block -> 32 live dest regs, issued
    // back-to-back. Offsets in bytes: 256 floats = 1024B apart.
    asm volatile(
        "ld.global.nc.L2::evict_first.v8.b32 {%0,%1,%2,%3,%4,%5,%6,%7}, [%32];\n\t"
        "ld.global.nc.L2::evict_first.v8.b32 {%8,%9,%10,%11,%12,%13,%14,%15}, [%32+1024];\n\t"
        "ld.global.nc.L2::evict_first.v8.b32 {%16,%17,%18,%19,%20,%21,%22,%23}, [%32+2048];\n\t"
        "ld.global.nc.L2::evict_first.v8.b32 {%24,%25,%26,%27,%28,%29,%30,%31}, [%32+3072];"
        : "=f"(f0),  "=f"(f1),  "=f"(f2),  "=f"(f3),
          "=f"(f4),  "=f"(f5),  "=f"(f6),  "=f"(f7),
          "=f"(f8),  "=f"(f9),  "=f"(f10), "=f"(f11),
          "=f"(f12), "=f"(f13), "=f"(f14), "=f"(f15),
          "=f"(f16), "=f"(f17), "=f"(f18), "=f"(f19),
          "=f"(f20), "=f"(f21), "=f"(f22), "=f"(f23),
          "=f"(f24), "=f"(f25), "=f"(f26), "=f"(f27),
          "=f"(f28), "=f"(f29), "=f"(f30), "=f"(f31)
        : "l"(row));

    float s0 = ((f0  + f1)  + (f2  + f3))  + ((f4  + f5)  + (f6  + f7));
    float s1 = ((f8  + f9)  + (f10 + f11)) + ((f12 + f13) + (f14 + f15));
    float s2 = ((f16 + f17) + (f18 + f19)) + ((f20 + f21) + (f22 + f23));
    float s3 = ((f24 + f25) + (f26 + f27)) + ((f28 + f29) + (f30 + f31));
    float s = (s0 + s1) + (s2 + s3);

    // butterfly warp reduction
#pragma unroll
    for (int off = 16; off; off >>= 1)
        s += __shfl_xor_sync(0xFFFFFFFFu, s, off);

    if (lane == 0) {
        float c = 0.0f;
        for (int i = 0; i < n_coeffs; i++) c += coeffs[i];
        out[gwarp] = s * c;
    }
}

extern "C" void kernel_launch(void* const* d_in, const int* in_sizes, int n_in,
                              void* d_out, int out_size)
{
    const float* x      = (const float*)d_in[0];
    const float* coeffs = (const float*)d_in[1];
    float* out          = (float*)d_out;

    int nrows    = in_sizes[0] / 1024;   // 65536
    int n_coeffs = in_sizes[1];          // 10

    // 16 warps (rows) per 512-thread block
    int blocks = (nrows + 15) / 16;      // 4096
    spline_rowsum_v8mlp_kernel<<<blocks, 512>>>(x, coeffs, n_coeffs, out, nrows);
}